// round 2
// baseline (speedup 1.0000x reference)
#include <cuda_runtime.h>
#include <cstdint>

#define BATCH 16
#define NANCH 25200
#define NCLS  80
#define TOPK  2048
#define CAND  4096

// ---------------- scratch (no allocations allowed) ----------------
__device__ float  g_scores[BATCH * NANCH];
__device__ int    g_labels[BATCH * NANCH];
__device__ float  g_top_scores[BATCH * TOPK];
__device__ float4 g_top_boxes[BATCH * TOPK];
__device__ int    g_top_labels[BATCH * TOPK];

// ---------------- Stage 1: per-anchor max/argmax over classes ----------------
__global__ __launch_bounds__(256) void k_scores(const float* __restrict__ obj,
                                                const float* __restrict__ cls)
{
    int gwarp = (blockIdx.x * blockDim.x + threadIdx.x) >> 5;
    int lane  = threadIdx.x & 31;
    if (gwarp >= BATCH * NANCH) return;
    const float* p = cls + (size_t)gwarp * NCLS;

    float best = -1.0f; int bi = 0;
    #pragma unroll
    for (int k = lane; k < NCLS; k += 32) {
        float v = p[k];
        if (v > best) { best = v; bi = k; }  // ascending k -> first occurrence kept
    }
    #pragma unroll
    for (int off = 16; off; off >>= 1) {
        float ov = __shfl_down_sync(0xFFFFFFFFu, best, off);
        int   oi = __shfl_down_sync(0xFFFFFFFFu, bi,   off);
        if (ov > best || (ov == best && oi < bi)) { best = ov; bi = oi; }
    }
    if (lane == 0) {
        float s = obj[gwarp] * best;               // == max(obj*p) bitwise (monotone rounding)
        g_scores[gwarp] = (s > 0.25f) ? s : 0.0f;  // conf filter
        g_labels[gwarp] = bi;
    }
}

// ---------------- Stage 2: per-image radix-select + exact top-k sort ----------------
__global__ __launch_bounds__(1024) void k_select(const float4* __restrict__ boxes)
{
    __shared__ int                s_hist[256];
    __shared__ unsigned           s_prefix;
    __shared__ int                s_remaining;
    __shared__ int                s_cnt;
    __shared__ unsigned long long s_arr[CAND];  // 32KB

    const int b   = blockIdx.x;
    const int tid = threadIdx.x;
    const float* sc = g_scores + b * NANCH;

    if (tid == 0) { s_prefix = 0; s_remaining = TOPK; }

    // 4-pass MSD radix select on float-as-uint (all scores >= 0 -> order-preserving)
    const int iters = (NANCH + 1023) / 1024;
    for (int byte = 3; byte >= 0; --byte) {
        if (tid < 256) s_hist[tid] = 0;
        __syncthreads();
        unsigned prefix = s_prefix;
        int shift = byte * 8;
        for (int it = 0; it < iters; ++it) {
            int i = tid + it * 1024;
            bool ok = false; unsigned bin = 0;
            if (i < NANCH) {
                unsigned k = __float_as_uint(sc[i]);
                ok  = (byte == 3) || ((k >> (shift + 8)) == prefix);
                bin = (k >> shift) & 255u;
            }
            unsigned tag = ok ? bin : 0x100u;
            unsigned m = __match_any_sync(0xFFFFFFFFu, tag);
            int leader = __ffs(m) - 1;
            if (ok && (tid & 31) == leader) atomicAdd(&s_hist[bin], __popc(m));
        }
        __syncthreads();
        if (tid == 0) {
            int acc = 0, rem = s_remaining; unsigned sel = 0;
            for (int v = 255; v >= 0; --v) {
                int h = s_hist[v];
                if (acc + h >= rem) { sel = (unsigned)v; s_remaining = rem - acc; break; }
                acc += h;
            }
            s_prefix = (s_prefix << 8) | sel;
        }
        __syncthreads();
    }

    if (tid == 0) s_cnt = 0;
    __syncthreads();
    const unsigned T = s_prefix;  // key of the TOPK-th largest score

    for (int i = tid; i < NANCH; i += 1024) {
        unsigned k = __float_as_uint(sc[i]);
        bool take = (k > T) || (k == T && T > 0);
        if (take) {
            int p = atomicAdd(&s_cnt, 1);
            if (p < CAND)
                s_arr[p] = ((unsigned long long)k << 32) | (unsigned)(0xFFFFFFFFu - (unsigned)i);
        }
    }
    __syncthreads();
    int cnt = s_cnt; if (cnt > CAND) cnt = CAND;
    for (int p = cnt + tid; p < CAND; p += 1024) s_arr[p] = 0ull;
    __syncthreads();

    // bitonic sort descending (score desc, idx asc) -- pair-indexed: 2048 compares per pass
    for (int kk = 2; kk <= CAND; kk <<= 1) {
        for (int j = kk >> 1; j > 0; j >>= 1) {
            #pragma unroll
            for (int p = tid; p < CAND / 2; p += 1024) {
                int i = ((p & ~(j - 1)) << 1) | (p & (j - 1));
                int l = i | j;
                unsigned long long a = s_arr[i], c = s_arr[l];
                bool desc = ((i & kk) == 0);
                if (desc ? (a < c) : (a > c)) { s_arr[i] = c; s_arr[l] = a; }
            }
            __syncthreads();
        }
    }

    // emit sorted top-K intermediates (+ gather boxes/labels)
    for (int j = tid; j < TOPK; j += 1024) {
        unsigned long long c = s_arr[j];
        unsigned key = (unsigned)(c >> 32);
        int o = b * TOPK + j;
        g_top_scores[o] = __uint_as_float(key);
        if (key) {
            unsigned idx = 0xFFFFFFFFu - (unsigned)(c & 0xFFFFFFFFull);
            g_top_boxes[o]  = boxes[(size_t)b * NANCH + idx];
            g_top_labels[o] = g_labels[b * NANCH + idx];
        } else {
            g_top_boxes[o]  = make_float4(0.f, 0.f, 0.f, 0.f);
            g_top_labels[o] = 0;
        }
    }
}

// ---------------- Stage 3: fused exact greedy NMS (chunked, all in shared) ----------------
// keep[i] = keep0[i] && no earlier kept j with iou(j,i) > 0.45. Chunks of 64:
// intra-chunk 64x64 bitmask + single-thread exact resolution, then bulk parallel
// suppression of all later boxes by the chunk's kept set.
__global__ __launch_bounds__(1024) void k_nms_fused(float* __restrict__ out_boxes,
                                                    float* __restrict__ out_scores,
                                                    float* __restrict__ out_labels)
{
    __shared__ float4             sbox[TOPK];    // 32KB
    __shared__ float              sarea[TOPK];   // 8KB
    __shared__ unsigned char      s_sup[TOPK];   // 2KB  (1 = suppressed or conf-failed)
    __shared__ unsigned long long s_cm[64];      // intra-chunk mask rows
    __shared__ int                s_kept[64];
    __shared__ int                s_m;
    __shared__ unsigned           s_aliveH[2];

    const int b = blockIdx.x, tid = threadIdx.x;

    for (int j = tid; j < TOPK; j += 1024) {
        float4 v = g_top_boxes[b * TOPK + j];
        sbox[j]  = v;
        sarea[j] = (v.z - v.x) * (v.w - v.y);               // same op order as reference
        s_sup[j] = (g_top_scores[b * TOPK + j] > 0.0f) ? 0 : 1;
    }
    __syncthreads();

    for (int g = 0; g < 32; ++g) {
        const int base = g << 6;

        if (tid < 64) s_cm[tid] = 0ull;
        if (tid < 64) {
            int alive = s_sup[base + tid] ? 0 : 1;
            unsigned bal = __ballot_sync(0xFFFFFFFFu, alive);
            if ((tid & 31) == 0) s_aliveH[tid >> 5] = bal;
        }
        __syncthreads();

        unsigned long long aliveM =
            ((unsigned long long)s_aliveH[1] << 32) | (unsigned long long)s_aliveH[0];

        // intra-chunk mask: 4096 pair slots, 4 per thread
        if (aliveM) {
            #pragma unroll
            for (int it = 0; it < 4; ++it) {
                int p = tid + it * 1024;
                int i = p >> 6, j = p & 63;
                if (j > i && !s_sup[base + i] && !s_sup[base + j]) {
                    float4 bi = sbox[base + i], bj = sbox[base + j];
                    float ltx = fmaxf(bi.x, bj.x), lty = fmaxf(bi.y, bj.y);
                    float rbx = fminf(bi.z, bj.z), rby = fminf(bi.w, bj.w);
                    float w = rbx - ltx, h = rby - lty;
                    if (w > 0.0f && h > 0.0f) {
                        float inter = w * h;
                        float iou = __fdiv_rn(inter, (sarea[base + i] + sarea[base + j]) - inter);
                        if (iou > 0.45f) atomicOr(&s_cm[i], 1ull << j);
                    }
                }
            }
        }
        __syncthreads();

        // exact greedy resolution inside the chunk (single thread, shared only)
        if (tid == 0) {
            unsigned long long rem = 0ull, cand = aliveM;
            int m = 0;
            while (cand) {
                int i = __ffsll(cand) - 1;          // lowest surviving index = next kept
                s_kept[m++] = base + i;
                rem |= s_cm[i];                      // bits only at j > i
                cand &= ~(1ull << i);
                cand &= ~rem;
            }
            s_m = m;
            unsigned long long supbits = aliveM & rem;
            while (supbits) {
                int i = __ffsll(supbits) - 1;
                supbits &= supbits - 1;
                s_sup[base + i] = 1;
            }
        }
        __syncthreads();

        // bulk suppression of all later boxes by this chunk's kept set
        const int m = s_m;
        if (m > 0) {
            for (int j = base + 64 + tid; j < TOPK; j += 1024) {
                if (!s_sup[j]) {
                    float4 bj = sbox[j];
                    float  aj = sarea[j];
                    for (int t = 0; t < m; ++t) {
                        int i = s_kept[t];
                        float4 bi = sbox[i];
                        float ltx = fmaxf(bi.x, bj.x), lty = fmaxf(bi.y, bj.y);
                        float rbx = fminf(bi.z, bj.z), rby = fminf(bi.w, bj.w);
                        float w = rbx - ltx, h = rby - lty;
                        if (w > 0.0f && h > 0.0f) {
                            float inter = w * h;
                            float iou = __fdiv_rn(inter, (sarea[i] + aj) - inter);
                            if (iou > 0.45f) { s_sup[j] = 1; break; }
                        }
                    }
                }
            }
        }
        __syncthreads();
    }

    // outputs: boxes [B,K,4], scores [B,K], labels [B,K] (float); suppressed -> 0
    for (int j = tid; j < TOPK; j += 1024) {
        int o = b * TOPK + j;
        bool kp = (s_sup[j] == 0);
        float f = kp ? 1.0f : 0.0f;
        float4 bx = sbox[j];
        out_boxes[o * 4 + 0] = bx.x * f;
        out_boxes[o * 4 + 1] = bx.y * f;
        out_boxes[o * 4 + 2] = bx.z * f;
        out_boxes[o * 4 + 3] = bx.w * f;
        out_scores[o] = kp ? g_top_scores[o] : 0.0f;
        out_labels[o] = kp ? (float)g_top_labels[o] : 0.0f;
    }
}

// ---------------- launch ----------------
extern "C" void kernel_launch(void* const* d_in, const int* in_sizes, int n_in,
                              void* d_out, int out_size)
{
    const float* boxes = (const float*)d_in[0];   // [16,25200,4]
    const float* obj   = (const float*)d_in[1];   // [16,25200]
    const float* cls   = (const float*)d_in[2];   // [16,25200,80]
    float* out = (float*)d_out;

    (void)in_sizes; (void)n_in; (void)out_size;

    int rows = BATCH * NANCH;
    int blocks1 = (rows * 32 + 255) / 256;         // warp per row
    k_scores<<<blocks1, 256>>>(obj, cls);

    k_select<<<BATCH, 1024>>>((const float4*)boxes);

    float* out_boxes  = out;
    float* out_scores = out + (size_t)BATCH * TOPK * 4;
    float* out_labels = out + (size_t)BATCH * TOPK * 5;
    k_nms_fused<<<BATCH, 1024>>>(out_boxes, out_scores, out_labels);
}

// round 7
// speedup vs baseline: 1.1624x; 1.1624x over previous
#include <cuda_runtime.h>
#include <cstdint>

#define BATCH 16
#define NANCH 25200
#define NCLS  80
#define TOPK  2048
#define CAND  4096
#define FULLM 0xFFFFFFFFu

// ---------------- scratch (no allocations allowed) ----------------
__device__ float              g_scores[BATCH * NANCH];
__device__ int                g_labels[BATCH * NANCH];
__device__ float              g_top_scores[BATCH * TOPK];
__device__ float4             g_top_boxes[BATCH * TOPK];
__device__ int                g_top_labels[BATCH * TOPK];
__device__ unsigned long long g_mask[(size_t)BATCH * TOPK * 32]; // successor masks (j>i), 8MB
__device__ unsigned long long g_rownz[BATCH * 32];               // per-row nonzero bitmap

// ---------------- Stage 1: per-anchor max/argmax over classes ----------------
// warp-per-row, redux-based argmax (first-occurrence tie-break).
__global__ __launch_bounds__(256) void k_scores(const float* __restrict__ obj,
                                                const float* __restrict__ cls)
{
    int gwarp = (blockIdx.x * 256 + threadIdx.x) >> 5;
    int lane  = threadIdx.x & 31;
    if (gwarp >= BATCH * NANCH) return;
    const float* p = cls + (size_t)gwarp * NCLS;

    // probs are non-negative -> float bits are order-preserving as u32
    unsigned b0 = __float_as_uint(p[lane]);
    unsigned b1 = __float_as_uint(p[lane + 32]);
    unsigned b2 = (lane < 16) ? __float_as_uint(p[lane + 64]) : 0u;
    unsigned lm = max(b0, max(b1, b2));
    unsigned m  = __reduce_max_sync(FULLM, lm);

    unsigned idx;
    if (b0 == m)                    idx = (unsigned)lane;         // ascending check -> min k per lane
    else if (b1 == m)               idx = (unsigned)(lane + 32);
    else if (lane < 16 && b2 == m)  idx = (unsigned)(lane + 64);
    else                            idx = 0x7FFFFFFFu;
    unsigned mi = __reduce_min_sync(FULLM, idx);

    if (lane == 0) {
        float s = obj[gwarp] * __uint_as_float(m);  // == max(obj*p) bitwise (monotone rounding)
        g_scores[gwarp] = (s > 0.25f) ? s : 0.0f;   // conf filter
        g_labels[gwarp] = (int)mi;
    }
}

// ---------------- Stage 2: per-image radix-select + exact top-k sort ----------------
__global__ __launch_bounds__(1024) void k_select(const float4* __restrict__ boxes)
{
    __shared__ unsigned long long s_arr[CAND];  // 32KB; first 16KB doubles as priv hist during radix
    __shared__ int                s_hist[256];
    __shared__ unsigned           s_prefix;
    __shared__ int                s_remaining;
    __shared__ int                s_cnt;

    const int b    = blockIdx.x;
    const int tid  = threadIdx.x;
    const int warp = tid >> 5;
    const int lane = tid & 31;
    const float* sc = g_scores + b * NANCH;
    unsigned short* priv = (unsigned short*)s_arr;   // [32][256] u16

    if (tid == 0) { s_prefix = 0; s_remaining = TOPK; }
    if (tid < 32) g_rownz[b * 32 + tid] = 0ull;      // zero nz bitmap for stage 3

    const int iters = (NANCH + 1023) / 1024;         // uniform trip count everywhere below
    for (int byte = 3; byte >= 0; --byte) {
        for (int i = tid; i < 32 * 256 / 2; i += 1024) ((unsigned*)priv)[i] = 0;
        __syncthreads();
        unsigned prefix = s_prefix;
        int shift = byte * 8;
        for (int it = 0; it < iters; ++it) {
            int i = tid + it * 1024;
            unsigned tag = 0x100u;
            if (i < NANCH) {
                unsigned k = __float_as_uint(sc[i]);
                bool ok = (byte == 3) || ((k >> (shift + 8)) == prefix);
                if (ok) tag = (k >> shift) & 255u;
            }
            unsigned mm = __match_any_sync(FULLM, tag);
            if (tag != 0x100u && (unsigned)(__ffs(mm) - 1) == (unsigned)lane) {
                int a = warp * 256 + (int)tag;       // warp-private row: no atomics needed
                priv[a] = (unsigned short)(priv[a] + __popc(mm));
            }
        }
        __syncthreads();
        if (tid < 256) {
            int sum = 0;
            #pragma unroll
            for (int w = 0; w < 32; ++w) sum += priv[w * 256 + tid];
            s_hist[tid] = sum;
        }
        __syncthreads();
        if (tid == 0) {
            int acc = 0, rem = s_remaining; unsigned sel = 0;
            for (int v = 255; v >= 0; --v) {
                int h = s_hist[v];
                if (acc + h >= rem) { sel = (unsigned)v; s_remaining = rem - acc; break; }
                acc += h;
            }
            s_prefix = (s_prefix << 8) | sel;
        }
        __syncthreads();
    }

    if (tid == 0) s_cnt = 0;
    __syncthreads();
    const unsigned T = s_prefix;  // key of the TOPK-th largest score

    // ballot-aggregated candidate gather — uniform trip count, predicate feeds ballot
    for (int it = 0; it < iters; ++it) {
        int i = tid + it * 1024;
        bool take = false; unsigned k = 0;
        if (i < NANCH) {
            k = __float_as_uint(sc[i]);
            take = (k > T) || (k == T && T > 0);
        }
        unsigned bal = __ballot_sync(FULLM, take);
        if (bal) {
            int leader = __ffs(bal) - 1;
            int pos = 0;
            if (lane == leader) pos = atomicAdd(&s_cnt, __popc(bal));
            pos = __shfl_sync(FULLM, pos, leader);
            if (take) {
                int my = pos + __popc(bal & ((1u << lane) - 1u));
                if (my < CAND)
                    s_arr[my] = ((unsigned long long)k << 32) | (unsigned)(0xFFFFFFFFu - (unsigned)i);
            }
        }
    }
    __syncthreads();
    int cnt = s_cnt; if (cnt > CAND) cnt = CAND;
    for (int p = cnt + tid; p < CAND; p += 1024) s_arr[p] = 0ull;
    __syncthreads();

    // bitonic sort descending on (score desc, idx asc) -- matches lax.top_k exactly
    for (int kk = 2; kk <= CAND; kk <<= 1) {
        for (int j = kk >> 1; j > 0; j >>= 1) {
            for (int p = tid; p < CAND / 2; p += 1024) {
                int i = ((p & ~(j - 1)) << 1) | (p & (j - 1));
                int l = i | j;
                unsigned long long a = s_arr[i], c = s_arr[l];
                bool desc = ((i & kk) == 0);
                if (desc ? (a < c) : (a > c)) { s_arr[i] = c; s_arr[l] = a; }
            }
            __syncthreads();
        }
    }

    for (int j = tid; j < TOPK; j += 1024) {
        unsigned long long c = s_arr[j];
        unsigned key = (unsigned)(c >> 32);
        int o = b * TOPK + j;
        g_top_scores[o] = __uint_as_float(key);
        if (key) {
            unsigned idx = 0xFFFFFFFFu - (unsigned)(c & 0xFFFFFFFFull);
            g_top_boxes[o]  = boxes[(size_t)b * NANCH + idx];
            g_top_labels[o] = g_labels[b * NANCH + idx];
        } else {
            g_top_boxes[o]  = make_float4(0.f, 0.f, 0.f, 0.f);
            g_top_labels[o] = 0;
        }
    }
}

// ---------------- Stage 3a: successor IoU bitmask (j > i) + nonzero bitmap ----------------
__global__ __launch_bounds__(256) void k_mask()
{
    __shared__ float4 sbox[TOPK];   // 32KB
    __shared__ float  sarea[TOPK];  // 8KB
    const int b   = blockIdx.y;
    const int tid = threadIdx.x;
    for (int j = tid; j < TOPK; j += 256) {
        float4 v = g_top_boxes[b * TOPK + j];
        sbox[j]  = v;
        sarea[j] = (v.z - v.x) * (v.w - v.y);   // same op order as reference
    }
    __syncthreads();

    const int warp = tid >> 5, lane = tid & 31;
    const int i = blockIdx.x * 8 + warp;
    const float4 bi = sbox[i];
    const float  ai = sarea[i];

    unsigned long long word = 0ull;
    int j0 = lane * 64;
    int js = (j0 > i + 1) ? j0 : (i + 1);   // successors only
    int je = j0 + 64;
    for (int j = js; j < je; ++j) {
        float4 bj = sbox[j];
        float ltx = fmaxf(bi.x, bj.x), lty = fmaxf(bi.y, bj.y);
        float rbx = fminf(bi.z, bj.z), rby = fminf(bi.w, bj.w);
        float w = rbx - ltx, h = rby - lty;
        if (w > 0.0f && h > 0.0f) {
            float inter = w * h;
            float iou = __fdiv_rn(inter, (ai + sarea[j]) - inter); // IEEE div
            if (iou > 0.45f) word |= 1ull << (j & 63);
        }
    }
    g_mask[((size_t)(b * TOPK + i)) * 32 + lane] = word;
    unsigned nzb = __ballot_sync(FULLM, word != 0ull);
    if (lane == 0 && nzb)
        atomicOr(&g_rownz[b * 32 + (i >> 6)], 1ull << (i & 63));
}

// ---------------- Stage 3b: warp-serial greedy resolve with zero-row skipping ----------------
__global__ __launch_bounds__(1024) void k_resolve(float* __restrict__ out_boxes,
                                                  float* __restrict__ out_scores,
                                                  float* __restrict__ out_labels)
{
    __shared__ unsigned long long s_alive[32], s_keep[32];
    const int b = blockIdx.x, tid = threadIdx.x, warp = tid >> 5, lane = tid & 31;

    // alive bits: warp w covers rows [w*64, w*64+64)
    {
        bool a0 = g_top_scores[b * TOPK + warp * 64 + lane] > 0.0f;
        bool a1 = g_top_scores[b * TOPK + warp * 64 + 32 + lane] > 0.0f;
        unsigned lo = __ballot_sync(FULLM, a0);
        unsigned hi = __ballot_sync(FULLM, a1);
        if (lane == 0) s_alive[warp] = ((unsigned long long)hi << 32) | (unsigned long long)lo;
    }
    __syncthreads();

    if (warp == 0) {
        unsigned long long rm   = 0ull;                    // lane w owns removed word w
        unsigned long long nzw  = g_rownz[b * 32 + lane];
        unsigned long long alv  = s_alive[lane];
        const size_t base = (size_t)b * TOPK;

        for (int blk = 0; blk < 32; ++blk) {
            unsigned long long rmB  = __shfl_sync(FULLM, rm,  blk);
            unsigned long long alB  = __shfl_sync(FULLM, alv, blk);
            unsigned long long nzB  = __shfl_sync(FULLM, nzw, blk);
            unsigned long long cand = alB & ~rmB & nzB;    // only rows that can suppress
            unsigned long long rem = 0ull, keptnz = 0ull;

            while (cand) {
                // lane t takes the t-th set bit of cand
                unsigned long long cc = cand;
                for (int t = 0; t < lane && cc; ++t) cc &= cc - 1;
                bool has = (cc != 0ull);
                int  r   = has ? (__ffsll((long long)cc) - 1) : 0;
                unsigned long long sub = 0ull;
                if (has)
                    sub = g_mask[(base + (size_t)(blk * 64 + r)) * 32 + blk]; // intra-block word
                int m = __popcll(cand); if (m > 32) m = 32;
                for (int t = 0; t < m; ++t) {
                    int rt = __shfl_sync(FULLM, r, t);
                    unsigned long long st = __shfl_sync(FULLM, sub, t);
                    if (!((rem >> rt) & 1ull)) { rem |= st; keptnz |= 1ull << rt; }
                }
                unsigned long long cc31 = __shfl_sync(FULLM, cc & (cc - 1ull), 31); // beyond 32nd
                cand = cc31 & ~rem;
            }

            // full-row OR for kept nz rows (independent loads -> MLP)
            unsigned long long kz = keptnz;
            while (kz) {
                int r = __ffsll((long long)kz) - 1; kz &= kz - 1ull;
                rm |= g_mask[(base + (size_t)(blk * 64 + r)) * 32 + lane];
            }
            if (lane == blk) rm |= rem;   // intra-block removals (redundant-safe)
        }
        s_keep[lane] = alv & ~rm;
    }
    __syncthreads();

    for (int j = tid; j < TOPK; j += 1024) {
        int o = b * TOPK + j;
        bool kp = ((s_keep[j >> 6] >> (j & 63)) & 1ull) != 0ull;
        float f = kp ? 1.0f : 0.0f;
        float4 bx = g_top_boxes[o];
        out_boxes[o * 4 + 0] = bx.x * f;
        out_boxes[o * 4 + 1] = bx.y * f;
        out_boxes[o * 4 + 2] = bx.z * f;
        out_boxes[o * 4 + 3] = bx.w * f;
        out_scores[o] = kp ? g_top_scores[o] : 0.0f;
        out_labels[o] = kp ? (float)g_top_labels[o] : 0.0f;
    }
}

// ---------------- launch ----------------
extern "C" void kernel_launch(void* const* d_in, const int* in_sizes, int n_in,
                              void* d_out, int out_size)
{
    const float* boxes = (const float*)d_in[0];   // [16,25200,4]
    const float* obj   = (const float*)d_in[1];   // [16,25200]
    const float* cls   = (const float*)d_in[2];   // [16,25200,80]
    float* out = (float*)d_out;

    (void)in_sizes; (void)n_in; (void)out_size;

    int rows = BATCH * NANCH;
    int blocks1 = (rows * 32 + 255) / 256;         // warp per row
    k_scores<<<blocks1, 256>>>(obj, cls);

    k_select<<<BATCH, 1024>>>((const float4*)boxes);

    dim3 gm(TOPK / 8, BATCH);
    k_mask<<<gm, 256>>>();

    float* out_boxes  = out;
    float* out_scores = out + (size_t)BATCH * TOPK * 4;
    float* out_labels = out + (size_t)BATCH * TOPK * 5;
    k_resolve<<<BATCH, 1024>>>(out_boxes, out_scores, out_labels);
}

// round 9
// speedup vs baseline: 1.4842x; 1.2768x over previous
#include <cuda_runtime.h>
#include <cstdint>

#define BATCH 16
#define NANCH 25200
#define NCLS  80
#define TOPK  2048
#define CAND  4096
#define FULLM 0xFFFFFFFFu

// ---------------- scratch (no allocations allowed) ----------------
__device__ float              g_scores[BATCH * NANCH];
__device__ int                g_labels[BATCH * NANCH];
__device__ float              g_top_scores[BATCH * TOPK];
__device__ float4             g_top_boxes[BATCH * TOPK];
__device__ int                g_top_labels[BATCH * TOPK];
__device__ unsigned long long g_mask[(size_t)BATCH * TOPK * 32]; // successor masks (j>i), 8MB
__device__ unsigned long long g_rownz[BATCH * 32];               // per-row nonzero bitmap

// ---------------- Stage 1: per-anchor max/argmax over classes ----------------
__global__ __launch_bounds__(256) void k_scores(const float* __restrict__ obj,
                                                const float* __restrict__ cls)
{
    int gwarp = (blockIdx.x * 256 + threadIdx.x) >> 5;
    int lane  = threadIdx.x & 31;
    if (gwarp >= BATCH * NANCH) return;
    const float* p = cls + (size_t)gwarp * NCLS;

    // probs are non-negative -> float bits are order-preserving as u32
    unsigned b0 = __float_as_uint(p[lane]);
    unsigned b1 = __float_as_uint(p[lane + 32]);
    unsigned b2 = (lane < 16) ? __float_as_uint(p[lane + 64]) : 0u;
    unsigned lm = max(b0, max(b1, b2));
    unsigned m  = __reduce_max_sync(FULLM, lm);

    unsigned idx;
    if (b0 == m)                    idx = (unsigned)lane;
    else if (b1 == m)               idx = (unsigned)(lane + 32);
    else if (lane < 16 && b2 == m)  idx = (unsigned)(lane + 64);
    else                            idx = 0x7FFFFFFFu;
    unsigned mi = __reduce_min_sync(FULLM, idx);

    if (lane == 0) {
        float s = obj[gwarp] * __uint_as_float(m);  // == max(obj*p) bitwise (monotone rounding)
        g_scores[gwarp] = (s > 0.25f) ? s : 0.0f;   // conf filter
        g_labels[gwarp] = (int)mi;
    }
}

// ---------------- Stage 2: per-image radix-select + exact top-k sort ----------------
__global__ __launch_bounds__(1024) void k_select(const float4* __restrict__ boxes)
{
    __shared__ unsigned long long s_arr[CAND];  // 32KB; first 16KB doubles as priv hist during radix
    __shared__ int                s_hist[256];
    __shared__ unsigned           s_prefix;
    __shared__ int                s_remaining;
    __shared__ int                s_cnt;

    const int b    = blockIdx.x;
    const int tid  = threadIdx.x;
    const int warp = tid >> 5;
    const int lane = tid & 31;
    const float* sc = g_scores + b * NANCH;
    unsigned short* priv = (unsigned short*)s_arr;   // [32][256] u16

    if (tid == 0) { s_prefix = 0; s_remaining = TOPK; }
    if (tid < 32) g_rownz[b * 32 + tid] = 0ull;

    const int iters = (NANCH + 1023) / 1024;         // uniform trip count everywhere below
    for (int byte = 3; byte >= 0; --byte) {
        for (int i = tid; i < 32 * 256 / 2; i += 1024) ((unsigned*)priv)[i] = 0;
        __syncthreads();
        unsigned prefix = s_prefix;
        int shift = byte * 8;
        for (int it = 0; it < iters; ++it) {
            int i = tid + it * 1024;
            unsigned tag = 0x100u;
            if (i < NANCH) {
                unsigned k = __float_as_uint(sc[i]);
                bool ok = (byte == 3) || ((k >> (shift + 8)) == prefix);
                if (ok) tag = (k >> shift) & 255u;
            }
            unsigned mm = __match_any_sync(FULLM, tag);
            if (tag != 0x100u && (unsigned)(__ffs(mm) - 1) == (unsigned)lane) {
                int a = warp * 256 + (int)tag;       // warp-private row: no atomics
                priv[a] = (unsigned short)(priv[a] + __popc(mm));
            }
        }
        __syncthreads();
        if (tid < 256) {
            int sum = 0;
            #pragma unroll
            for (int w = 0; w < 32; ++w) sum += priv[w * 256 + tid];
            s_hist[tid] = sum;
        }
        __syncthreads();
        if (tid == 0) {
            int acc = 0, rem = s_remaining; unsigned sel = 0;
            for (int v = 255; v >= 0; --v) {
                int h = s_hist[v];
                if (acc + h >= rem) { sel = (unsigned)v; s_remaining = rem - acc; break; }
                acc += h;
            }
            s_prefix = (s_prefix << 8) | sel;
        }
        __syncthreads();
    }

    if (tid == 0) s_cnt = 0;
    __syncthreads();
    const unsigned T = s_prefix;

    // ballot-aggregated candidate gather — uniform trip count, predicate feeds ballot
    for (int it = 0; it < iters; ++it) {
        int i = tid + it * 1024;
        bool take = false; unsigned k = 0;
        if (i < NANCH) {
            k = __float_as_uint(sc[i]);
            take = (k > T) || (k == T && T > 0);
        }
        unsigned bal = __ballot_sync(FULLM, take);
        if (bal) {
            int leader = __ffs(bal) - 1;
            int pos = 0;
            if (lane == leader) pos = atomicAdd(&s_cnt, __popc(bal));
            pos = __shfl_sync(FULLM, pos, leader);
            if (take) {
                int my = pos + __popc(bal & ((1u << lane) - 1u));
                if (my < CAND)
                    s_arr[my] = ((unsigned long long)k << 32) | (unsigned)(0xFFFFFFFFu - (unsigned)i);
            }
        }
    }
    __syncthreads();
    int cnt = s_cnt; if (cnt > CAND) cnt = CAND;
    for (int p = cnt + tid; p < CAND; p += 1024) s_arr[p] = 0ull;
    __syncthreads();

    // bitonic sort descending on (score desc, idx asc) -- matches lax.top_k exactly
    for (int kk = 2; kk <= CAND; kk <<= 1) {
        for (int j = kk >> 1; j > 0; j >>= 1) {
            for (int p = tid; p < CAND / 2; p += 1024) {
                int i = ((p & ~(j - 1)) << 1) | (p & (j - 1));
                int l = i | j;
                unsigned long long a = s_arr[i], c = s_arr[l];
                bool desc = ((i & kk) == 0);
                if (desc ? (a < c) : (a > c)) { s_arr[i] = c; s_arr[l] = a; }
            }
            __syncthreads();
        }
    }

    for (int j = tid; j < TOPK; j += 1024) {
        unsigned long long c = s_arr[j];
        unsigned key = (unsigned)(c >> 32);
        int o = b * TOPK + j;
        g_top_scores[o] = __uint_as_float(key);
        if (key) {
            unsigned idx = 0xFFFFFFFFu - (unsigned)(c & 0xFFFFFFFFull);
            g_top_boxes[o]  = boxes[(size_t)b * NANCH + idx];
            g_top_labels[o] = g_labels[b * NANCH + idx];
        } else {
            g_top_boxes[o]  = make_float4(0.f, 0.f, 0.f, 0.f);
            g_top_labels[o] = 0;
        }
    }
}

// ---------------- Stage 3a: successor IoU bitmask (j > i) + nonzero bitmap ----------------
__global__ __launch_bounds__(256) void k_mask()
{
    __shared__ float4 sbox[TOPK];   // 32KB
    __shared__ float  sarea[TOPK];  // 8KB
    const int b   = blockIdx.y;
    const int tid = threadIdx.x;
    for (int j = tid; j < TOPK; j += 256) {
        float4 v = g_top_boxes[b * TOPK + j];
        sbox[j]  = v;
        sarea[j] = (v.z - v.x) * (v.w - v.y);   // same op order as reference
    }
    __syncthreads();

    const int warp = tid >> 5, lane = tid & 31;
    const int i = blockIdx.x * 8 + warp;
    const float4 bi = sbox[i];
    const float  ai = sarea[i];

    unsigned long long word = 0ull;
    int j0 = lane * 64;
    int js = (j0 > i + 1) ? j0 : (i + 1);   // successors only
    int je = j0 + 64;
    for (int j = js; j < je; ++j) {
        float4 bj = sbox[j];
        float ltx = fmaxf(bi.x, bj.x), lty = fmaxf(bi.y, bj.y);
        float rbx = fminf(bi.z, bj.z), rby = fminf(bi.w, bj.w);
        float w = rbx - ltx, h = rby - lty;
        if (w > 0.0f && h > 0.0f) {
            float inter = w * h;
            float iou = __fdiv_rn(inter, (ai + sarea[j]) - inter); // IEEE div
            if (iou > 0.45f) word |= 1ull << (j & 63);
        }
    }
    g_mask[((size_t)(b * TOPK + i)) * 32 + lane] = word;
    unsigned nzb = __ballot_sync(FULLM, word != 0ull);
    if (lane == 0 && nzb)
        atomicOr(&g_rownz[b * 32 + (i >> 6)], 1ull << (i & 63));
}

// ---------------- Stage 3b: double-buffered shared-memory greedy resolve ----------------
// Warps 1-31 prefetch the next 64-row mask block (16KB contiguous) into shared
// while warp 0 resolves the current block entirely from shared memory.
__global__ __launch_bounds__(1024) void k_resolve(float* __restrict__ out_boxes,
                                                  float* __restrict__ out_scores,
                                                  float* __restrict__ out_labels)
{
    __shared__ unsigned long long s_buf[2][64 * 32];   // 2 x 16KB double buffer
    __shared__ unsigned long long s_alive[32], s_keep[32];
    const int b = blockIdx.x, tid = threadIdx.x, warp = tid >> 5, lane = tid & 31;

    // alive bits: warp w covers rows [w*64, w*64+64)
    {
        bool a0 = g_top_scores[b * TOPK + warp * 64 + lane] > 0.0f;
        bool a1 = g_top_scores[b * TOPK + warp * 64 + 32 + lane] > 0.0f;
        unsigned lo = __ballot_sync(FULLM, a0);
        unsigned hi = __ballot_sync(FULLM, a1);
        if (lane == 0) s_alive[warp] = ((unsigned long long)hi << 32) | (unsigned long long)lo;
    }

    const unsigned long long* mbase = g_mask + (size_t)b * TOPK * 32;

    // prefetch block 0 (all threads)
    for (int i = tid; i < 2048; i += 1024) s_buf[0][i] = mbase[i];
    __syncthreads();

    unsigned long long rm = 0ull, alv = 0ull, nzw = 0ull;  // lane w owns word w (warp 0)
    if (warp == 0) { nzw = g_rownz[b * 32 + lane]; alv = s_alive[lane]; }

    for (int g = 0; g < 32; ++g) {
        if (warp > 0) {
            // producer: prefetch block g+1
            if (g < 31) {
                const unsigned long long* src = mbase + (size_t)(g + 1) * 2048;
                unsigned long long* dst = s_buf[(g + 1) & 1];
                for (int i = tid - 32; i < 2048; i += 992) dst[i] = src[i];
            }
        } else {
            // consumer: resolve block g from shared
            const unsigned long long* buf = s_buf[g & 1];
            unsigned long long rmB = __shfl_sync(FULLM, rm,  g);
            unsigned long long alB = __shfl_sync(FULLM, alv, g);
            unsigned long long nzB = __shfl_sync(FULLM, nzw, g);
            unsigned long long cand = alB & ~rmB & nzB;   // only rows that can suppress
            unsigned long long rem = 0ull, kept = 0ull;

            while (cand) {                                 // uniform across the warp
                int r = __ffsll((long long)cand) - 1;
                cand &= cand - 1ull;
                kept |= 1ull << r;
                rem  |= buf[r * 32 + g];                   // broadcast LDS (diagonal word)
                cand &= ~rem;                              // prune suppressed candidates
            }
            if (lane == g) rm |= rem;

            // apply kept rows' full masks: 4 rotating accumulators to overlap LDS latency
            unsigned long long a0 = 0, a1 = 0, a2 = 0, a3 = 0;
            unsigned long long kz = kept;
            while (kz) {
                int r0 = __ffsll((long long)kz) - 1; kz &= kz - 1ull;
                a0 |= buf[r0 * 32 + lane];
                if (kz) { int r1 = __ffsll((long long)kz) - 1; kz &= kz - 1ull; a1 |= buf[r1 * 32 + lane]; }
                if (kz) { int r2 = __ffsll((long long)kz) - 1; kz &= kz - 1ull; a2 |= buf[r2 * 32 + lane]; }
                if (kz) { int r3 = __ffsll((long long)kz) - 1; kz &= kz - 1ull; a3 |= buf[r3 * 32 + lane]; }
            }
            rm |= (a0 | a1) | (a2 | a3);
        }
        __syncthreads();
    }

    if (warp == 0) s_keep[lane] = alv & ~rm;
    __syncthreads();

    for (int j = tid; j < TOPK; j += 1024) {
        int o = b * TOPK + j;
        bool kp = ((s_keep[j >> 6] >> (j & 63)) & 1ull) != 0ull;
        float f = kp ? 1.0f : 0.0f;
        float4 bx = g_top_boxes[o];
        out_boxes[o * 4 + 0] = bx.x * f;
        out_boxes[o * 4 + 1] = bx.y * f;
        out_boxes[o * 4 + 2] = bx.z * f;
        out_boxes[o * 4 + 3] = bx.w * f;
        out_scores[o] = kp ? g_top_scores[o] : 0.0f;
        out_labels[o] = kp ? (float)g_top_labels[o] : 0.0f;
    }
}

// ---------------- launch ----------------
extern "C" void kernel_launch(void* const* d_in, const int* in_sizes, int n_in,
                              void* d_out, int out_size)
{
    const float* boxes = (const float*)d_in[0];   // [16,25200,4]
    const float* obj   = (const float*)d_in[1];   // [16,25200]
    const float* cls   = (const float*)d_in[2];   // [16,25200,80]
    float* out = (float*)d_out;

    (void)in_sizes; (void)n_in; (void)out_size;

    int rows = BATCH * NANCH;
    int blocks1 = (rows * 32 + 255) / 256;         // warp per row
    k_scores<<<blocks1, 256>>>(obj, cls);

    k_select<<<BATCH, 1024>>>((const float4*)boxes);

    dim3 gm(TOPK / 8, BATCH);
    k_mask<<<gm, 256>>>();

    float* out_boxes  = out;
    float* out_scores = out + (size_t)BATCH * TOPK * 4;
    float* out_labels = out + (size_t)BATCH * TOPK * 5;
    k_resolve<<<BATCH, 1024>>>(out_boxes, out_scores, out_labels);
}